// round 2
// baseline (speedup 1.0000x reference)
#include <cuda_runtime.h>
#include <cuda_bf16.h>

// Problem constants
#define BATCH 512
#define CIN   3
#define HIMG  256
#define DIN   9216     // 3 scales * 3 ch * 32*32
#define HG    1024
#define HL    128
#define NOUT  1152     // HG + HL

// Scratch (no allocations allowed -> device globals)
__device__ float g_glimpse[BATCH * DIN];   // 18.9 MB
__device__ float g_h[BATCH * HG];          // 2 MB
__device__ float g_hw[BATCH * HL];         // 256 KB

// ---------------------------------------------------------------------------
// Foveation: for each (b, p, c, i, j) compute mean of k x k block (k = 2^p)
// centered per the reference's dynamic_slice-with-padding semantics.
// glimpse[b, ((p*3+c)*32+i)*32+j]
// ---------------------------------------------------------------------------
__global__ void foveate_kernel(const float* __restrict__ x,
                               const float* __restrict__ l)
{
    int idx = blockIdx.x * blockDim.x + threadIdx.x;
    if (idx >= BATCH * DIN) return;

    int b  = idx / DIN;
    int r  = idx % DIN;
    int pc = r >> 10;          // 0..8  (p*3 + c), 1024 = 32*32
    int i  = (r >> 5) & 31;
    int j  = r & 31;
    int p  = pc / 3;
    int c  = pc - 3 * p;
    int k  = 1 << p;           // 1, 2, 4
    int pad = 16 * k;          // size/2, size = 32*k

    float l0 = l[2 * b + 0];
    float l1 = l[2 * b + 1];
    // coords = floor(0.5 * ((l + 1) * [H, W])); fx = coords[:,0], fy = coords[:,1]
    int fx = (int)floorf(0.5f * ((l0 + 1.0f) * 256.0f));
    int fy = (int)floorf(0.5f * ((l1 + 1.0f) * 256.0f));
    // dynamic_slice start clamp on padded image: [0, H + 2*pad - size] = [0, 256]
    fx = min(max(fx, 0), 256);
    fy = min(max(fy, 0), 256);

    int y0 = fy + i * k - pad;  // top row of k x k block (unpadded coords)
    int x0 = fx + j * k - pad;

    const float* src = x + ((long long)b * CIN + c) * (HIMG * HIMG);
    float s = 0.0f;
    #pragma unroll 4
    for (int di = 0; di < k; ++di) {
        int y = y0 + di;
        if ((unsigned)y < 256u) {
            const float* row = src + y * HIMG;
            #pragma unroll 4
            for (int dj = 0; dj < k; ++dj) {
                int xx = x0 + dj;
                if ((unsigned)xx < 256u) s += row[xx];
            }
        }
    }
    g_glimpse[idx] = s / (float)(k * k);
}

// ---------------------------------------------------------------------------
// hw = relu(l @ W2^T + b2)   : (512,2) @ (2,128)
// ---------------------------------------------------------------------------
__global__ void where_kernel(const float* __restrict__ l,
                             const float* __restrict__ W2,
                             const float* __restrict__ b2)
{
    int idx = blockIdx.x * blockDim.x + threadIdx.x;
    if (idx >= BATCH * HL) return;
    int b = idx / HL;
    int n = idx % HL;
    float v = b2[n] + l[2 * b + 0] * W2[2 * n + 0] + l[2 * b + 1] * W2[2 * n + 1];
    g_hw[idx] = fmaxf(v, 0.0f);
}

// ---------------------------------------------------------------------------
// GEMM1: h = relu(glimpse @ W1^T + b1)
// A = g_glimpse (M=512, K=9216) row-major; W = W1 (N=1024, K=9216) row-major.
// Tiles 64x64, BK=16, 256 threads, 4x4 microtile.
// ---------------------------------------------------------------------------
__global__ __launch_bounds__(256)
void gemm1_kernel(const float* __restrict__ W1, const float* __restrict__ b1)
{
    const int N = HG, K = DIN;
    __shared__ float As[16][68];
    __shared__ float Ws[16][68];

    int tid = threadIdx.x;
    int m0 = blockIdx.y * 64;
    int n0 = blockIdx.x * 64;
    int tx = tid & 15;      // 0..15 -> n micro
    int ty = tid >> 4;      // 0..15 -> m micro
    int lr = tid >> 2;      // 0..63 row within tile
    int lk = (tid & 3) * 4; // 0,4,8,12

    float acc[4][4] = {};

    const float* Abase = g_glimpse + (long long)(m0 + lr) * K + lk;
    const float* Wbase = W1 + (long long)(n0 + lr) * K + lk;

    for (int k0 = 0; k0 < K; k0 += 16) {
        float4 a = *(const float4*)(Abase + k0);
        float4 w = *(const float4*)(Wbase + k0);
        As[lk + 0][lr] = a.x; As[lk + 1][lr] = a.y;
        As[lk + 2][lr] = a.z; As[lk + 3][lr] = a.w;
        Ws[lk + 0][lr] = w.x; Ws[lk + 1][lr] = w.y;
        Ws[lk + 2][lr] = w.z; Ws[lk + 3][lr] = w.w;
        __syncthreads();
        #pragma unroll
        for (int kk = 0; kk < 16; ++kk) {
            float av[4], wv[4];
            #pragma unroll
            for (int u = 0; u < 4; ++u) av[u] = As[kk][ty * 4 + u];
            #pragma unroll
            for (int u = 0; u < 4; ++u) wv[u] = Ws[kk][tx * 4 + u];
            #pragma unroll
            for (int mi = 0; mi < 4; ++mi)
                #pragma unroll
                for (int ni = 0; ni < 4; ++ni)
                    acc[mi][ni] += av[mi] * wv[ni];
        }
        __syncthreads();
    }

    #pragma unroll
    for (int mi = 0; mi < 4; ++mi) {
        int m = m0 + ty * 4 + mi;
        #pragma unroll
        for (int ni = 0; ni < 4; ++ni) {
            int n = n0 + tx * 4 + ni;
            float v = acc[mi][ni] + b1[n];
            g_h[(long long)m * N + n] = fmaxf(v, 0.0f);
        }
    }
}

// ---------------------------------------------------------------------------
// GEMM2 fused: out = relu(h @ W3^T + b3 + hw @ W4^T + b4)
// h (512,1024), W3 (1152,1024); hw (512,128), W4 (1152,128).
// ---------------------------------------------------------------------------
__global__ __launch_bounds__(256)
void gemm2_kernel(const float* __restrict__ W3, const float* __restrict__ b3,
                  const float* __restrict__ W4, const float* __restrict__ b4,
                  float* __restrict__ out)
{
    const int N = NOUT;
    __shared__ float As[16][68];
    __shared__ float Ws[16][68];

    int tid = threadIdx.x;
    int m0 = blockIdx.y * 64;
    int n0 = blockIdx.x * 64;
    int tx = tid & 15;
    int ty = tid >> 4;
    int lr = tid >> 2;
    int lk = (tid & 3) * 4;

    float acc[4][4] = {};

    // --- Part 1: h @ W3^T  (K = 1024) ---
    {
        const int K = HG;
        const float* Abase = g_h + (long long)(m0 + lr) * K + lk;
        const float* Wbase = W3 + (long long)(n0 + lr) * K + lk;
        for (int k0 = 0; k0 < K; k0 += 16) {
            float4 a = *(const float4*)(Abase + k0);
            float4 w = *(const float4*)(Wbase + k0);
            As[lk + 0][lr] = a.x; As[lk + 1][lr] = a.y;
            As[lk + 2][lr] = a.z; As[lk + 3][lr] = a.w;
            Ws[lk + 0][lr] = w.x; Ws[lk + 1][lr] = w.y;
            Ws[lk + 2][lr] = w.z; Ws[lk + 3][lr] = w.w;
            __syncthreads();
            #pragma unroll
            for (int kk = 0; kk < 16; ++kk) {
                float av[4], wv[4];
                #pragma unroll
                for (int u = 0; u < 4; ++u) av[u] = As[kk][ty * 4 + u];
                #pragma unroll
                for (int u = 0; u < 4; ++u) wv[u] = Ws[kk][tx * 4 + u];
                #pragma unroll
                for (int mi = 0; mi < 4; ++mi)
                    #pragma unroll
                    for (int ni = 0; ni < 4; ++ni)
                        acc[mi][ni] += av[mi] * wv[ni];
            }
            __syncthreads();
        }
    }

    // --- Part 2: hw @ W4^T  (K = 128) ---
    {
        const int K = HL;
        const float* Abase = g_hw + (long long)(m0 + lr) * K + lk;
        const float* Wbase = W4 + (long long)(n0 + lr) * K + lk;
        for (int k0 = 0; k0 < K; k0 += 16) {
            float4 a = *(const float4*)(Abase + k0);
            float4 w = *(const float4*)(Wbase + k0);
            As[lk + 0][lr] = a.x; As[lk + 1][lr] = a.y;
            As[lk + 2][lr] = a.z; As[lk + 3][lr] = a.w;
            Ws[lk + 0][lr] = w.x; Ws[lk + 1][lr] = w.y;
            Ws[lk + 2][lr] = w.z; Ws[lk + 3][lr] = w.w;
            __syncthreads();
            #pragma unroll
            for (int kk = 0; kk < 16; ++kk) {
                float av[4], wv[4];
                #pragma unroll
                for (int u = 0; u < 4; ++u) av[u] = As[kk][ty * 4 + u];
                #pragma unroll
                for (int u = 0; u < 4; ++u) wv[u] = Ws[kk][tx * 4 + u];
                #pragma unroll
                for (int mi = 0; mi < 4; ++mi)
                    #pragma unroll
                    for (int ni = 0; ni < 4; ++ni)
                        acc[mi][ni] += av[mi] * wv[ni];
            }
            __syncthreads();
        }
    }

    #pragma unroll
    for (int mi = 0; mi < 4; ++mi) {
        int m = m0 + ty * 4 + mi;
        #pragma unroll
        for (int ni = 0; ni < 4; ++ni) {
            int n = n0 + tx * 4 + ni;
            float v = acc[mi][ni] + b3[n] + b4[n];
            out[(long long)m * N + n] = fmaxf(v, 0.0f);
        }
    }
}

// ---------------------------------------------------------------------------
extern "C" void kernel_launch(void* const* d_in, const int* in_sizes, int n_in,
                              void* d_out, int out_size)
{
    const float* x  = (const float*)d_in[0];   // (512, 3, 256, 256)
    const float* l  = (const float*)d_in[1];   // (512, 2)
    const float* W1 = (const float*)d_in[2];   // (1024, 9216)
    const float* b1 = (const float*)d_in[3];   // (1024,)
    const float* W2 = (const float*)d_in[4];   // (128, 2)
    const float* b2 = (const float*)d_in[5];   // (128,)
    const float* W3 = (const float*)d_in[6];   // (1152, 1024)
    const float* b3 = (const float*)d_in[7];   // (1152,)
    const float* W4 = (const float*)d_in[8];   // (1152, 128)
    const float* b4 = (const float*)d_in[9];   // (1152,)
    float* out = (float*)d_out;                // (512, 1152)

    (void)in_sizes; (void)n_in; (void)out_size;

    // 1) foveation -> g_glimpse
    {
        int total = BATCH * DIN;
        foveate_kernel<<<(total + 255) / 256, 256>>>(x, l);
    }
    // 2) where path -> g_hw (independent of 1/3, cheap)
    {
        int total = BATCH * HL;
        where_kernel<<<(total + 255) / 256, 256>>>(l, W2, b2);
    }
    // 3) h = relu(glimpse @ W1^T + b1) -> g_h
    {
        dim3 grid(HG / 64, BATCH / 64);   // (16, 8)
        gemm1_kernel<<<grid, 256>>>(W1, b1);
    }
    // 4) out = relu(h @ W3^T + b3 + hw @ W4^T + b4)
    {
        dim3 grid(NOUT / 64, BATCH / 64); // (18, 8)
        gemm2_kernel<<<grid, 256>>>(W3, b3, W4, b4, out);
    }
}

// round 6
// speedup vs baseline: 2.0074x; 2.0074x over previous
#include <cuda_runtime.h>
#include <cuda_bf16.h>
#include <cstdint>

// Problem constants
#define BATCH 512
#define CIN   3
#define HIMG  256
#define DIN   9216     // 3 scales * 3 ch * 32*32
#define HG    1024
#define HL    128
#define NOUT  1152     // HG + HL

#define BM 64
#define BN 64
#define BK 32
#define SMS 73         // smem row stride (conflict-free for transposed STS)

// Scratch (no allocations allowed -> device globals)
__device__ float g_glimpse[BATCH * DIN];   // 18.9 MB
__device__ float g_h[BATCH * HG];          // 2 MB
__device__ float g_hw[BATCH * HL];         // 256 KB

// ---------------------------------------------------------------------------
// Foveation (unchanged from passing R2 kernel)
// ---------------------------------------------------------------------------
__global__ void foveate_kernel(const float* __restrict__ x,
                               const float* __restrict__ l)
{
    int idx = blockIdx.x * blockDim.x + threadIdx.x;
    if (idx >= BATCH * DIN) return;

    int b  = idx / DIN;
    int r  = idx % DIN;
    int pc = r >> 10;
    int i  = (r >> 5) & 31;
    int j  = r & 31;
    int p  = pc / 3;
    int c  = pc - 3 * p;
    int k  = 1 << p;
    int pad = 16 * k;

    float l0 = l[2 * b + 0];
    float l1 = l[2 * b + 1];
    int fx = (int)floorf(0.5f * ((l0 + 1.0f) * 256.0f));
    int fy = (int)floorf(0.5f * ((l1 + 1.0f) * 256.0f));
    fx = min(max(fx, 0), 256);
    fy = min(max(fy, 0), 256);

    int y0 = fy + i * k - pad;
    int x0 = fx + j * k - pad;

    const float* src = x + ((long long)b * CIN + c) * (HIMG * HIMG);
    float s = 0.0f;
    #pragma unroll 4
    for (int di = 0; di < k; ++di) {
        int y = y0 + di;
        if ((unsigned)y < 256u) {
            const float* row = src + y * HIMG;
            #pragma unroll 4
            for (int dj = 0; dj < k; ++dj) {
                int xx = x0 + dj;
                if ((unsigned)xx < 256u) s += row[xx];
            }
        }
    }
    g_glimpse[idx] = s / (float)(k * k);
}

// ---------------------------------------------------------------------------
// hw = relu(l @ W2^T + b2)
// ---------------------------------------------------------------------------
__global__ void where_kernel(const float* __restrict__ l,
                             const float* __restrict__ W2,
                             const float* __restrict__ b2)
{
    int idx = blockIdx.x * blockDim.x + threadIdx.x;
    if (idx >= BATCH * HL) return;
    int b = idx / HL;
    int n = idx % HL;
    float v = b2[n] + l[2 * b + 0] * W2[2 * n + 0] + l[2 * b + 1] * W2[2 * n + 1];
    g_hw[idx] = fmaxf(v, 0.0f);
}

// ---------------------------------------------------------------------------
// TF32 tensor-core GEMM machinery (m16n8k8 warp mma)
// ---------------------------------------------------------------------------
__device__ __forceinline__ uint32_t f2tf32(float f) {
    uint32_t u;
    asm("cvt.rna.tf32.f32 %0, %1;" : "=r"(u) : "f"(f));
    return u;
}

__device__ __forceinline__ void mma_tf32(float c[4],
                                         const uint32_t a[4],
                                         const uint32_t b[2]) {
    asm volatile(
        "mma.sync.aligned.m16n8k8.row.col.f32.tf32.tf32.f32 "
        "{%0,%1,%2,%3}, {%4,%5,%6,%7}, {%8,%9}, {%0,%1,%2,%3};"
        : "+f"(c[0]), "+f"(c[1]), "+f"(c[2]), "+f"(c[3])
        : "r"(a[0]), "r"(a[1]), "r"(a[2]), "r"(a[3]),
          "r"(b[0]), "r"(b[1]));
}

// Compute one BK=32 slab from smem buffers into acc[2][4][4].
__device__ __forceinline__ void mma_compute(const uint32_t* __restrict__ sa,
                                            const uint32_t* __restrict__ sb,
                                            int wm, int wn, int g, int t,
                                            float acc[2][4][4])
{
    #pragma unroll
    for (int ks = 0; ks < BK; ks += 8) {
        const uint32_t* pa0 = sa + (ks + t) * SMS;
        const uint32_t* pa4 = sa + (ks + t + 4) * SMS;
        const uint32_t* pb0 = sb + (ks + t) * SMS;
        const uint32_t* pb4 = sb + (ks + t + 4) * SMS;

        uint32_t af[2][4];
        #pragma unroll
        for (int sm = 0; sm < 2; ++sm) {
            int mm = wm + sm * 16 + g;
            af[sm][0] = pa0[mm];
            af[sm][1] = pa0[mm + 8];
            af[sm][2] = pa4[mm];
            af[sm][3] = pa4[mm + 8];
        }
        uint32_t bf[4][2];
        #pragma unroll
        for (int n8 = 0; n8 < 4; ++n8) {
            int nn = wn + n8 * 8 + g;
            bf[n8][0] = pb0[nn];
            bf[n8][1] = pb4[nn];
        }
        #pragma unroll
        for (int sm = 0; sm < 2; ++sm)
            #pragma unroll
            for (int n8 = 0; n8 < 4; ++n8)
                mma_tf32(acc[sm][n8], af[sm], bf[n8]);
    }
}

// One pipelined GEMM phase: acc += A[m0.., :K] @ W[n0.., :K]^T
// A: row-major (lda), W: row-major (ldw). K % 32 == 0.
__device__ __forceinline__ void gemm_phase(const float* __restrict__ A, int lda,
                                           const float* __restrict__ W, int ldw,
                                           int K, int m0, int n0,
                                           uint32_t (*sA)[BK * SMS],
                                           uint32_t (*sB)[BK * SMS],
                                           float acc[2][4][4])
{
    const int tid  = threadIdx.x;
    const int lane = tid & 31;
    const int warp = tid >> 5;
    const int wm = (warp >> 1) * 32;
    const int wn = (warp & 1) * 32;
    const int g = lane >> 2;
    const int t = lane & 3;

    const int nIter = K / BK;
    float4 ra[4], rb[4];

    // per-thread load coords: idx = tid + 128*i; row = idx>>3; k = (idx&7)*4
    int rowi[4], ki[4];
    #pragma unroll
    for (int i = 0; i < 4; ++i) {
        int idx = tid + 128 * i;
        rowi[i] = idx >> 3;
        ki[i]   = (idx & 7) * 4;
    }

    // prologue: load slab 0
    #pragma unroll
    for (int i = 0; i < 4; ++i) {
        ra[i] = *(const float4*)(A + (long long)(m0 + rowi[i]) * lda + ki[i]);
        rb[i] = *(const float4*)(W + (long long)(n0 + rowi[i]) * ldw + ki[i]);
    }
    #pragma unroll
    for (int i = 0; i < 4; ++i) {
        int base = ki[i] * SMS + rowi[i];
        sA[0][base + 0 * SMS] = f2tf32(ra[i].x);
        sA[0][base + 1 * SMS] = f2tf32(ra[i].y);
        sA[0][base + 2 * SMS] = f2tf32(ra[i].z);
        sA[0][base + 3 * SMS] = f2tf32(ra[i].w);
        sB[0][base + 0 * SMS] = f2tf32(rb[i].x);
        sB[0][base + 1 * SMS] = f2tf32(rb[i].y);
        sB[0][base + 2 * SMS] = f2tf32(rb[i].z);
        sB[0][base + 3 * SMS] = f2tf32(rb[i].w);
    }
    __syncthreads();

    for (int it = 0; it < nIter; ++it) {
        int nxt = it + 1;
        if (nxt < nIter) {
            int k0 = nxt * BK;
            #pragma unroll
            for (int i = 0; i < 4; ++i) {
                ra[i] = *(const float4*)(A + (long long)(m0 + rowi[i]) * lda + k0 + ki[i]);
                rb[i] = *(const float4*)(W + (long long)(n0 + rowi[i]) * ldw + k0 + ki[i]);
            }
        }

        mma_compute(sA[it & 1], sB[it & 1], wm, wn, g, t, acc);

        if (nxt < nIter) {
            int buf = nxt & 1;
            #pragma unroll
            for (int i = 0; i < 4; ++i) {
                int base = ki[i] * SMS + rowi[i];
                sA[buf][base + 0 * SMS] = f2tf32(ra[i].x);
                sA[buf][base + 1 * SMS] = f2tf32(ra[i].y);
                sA[buf][base + 2 * SMS] = f2tf32(ra[i].z);
                sA[buf][base + 3 * SMS] = f2tf32(ra[i].w);
                sB[buf][base + 0 * SMS] = f2tf32(rb[i].x);
                sB[buf][base + 1 * SMS] = f2tf32(rb[i].y);
                sB[buf][base + 2 * SMS] = f2tf32(rb[i].z);
                sB[buf][base + 3 * SMS] = f2tf32(rb[i].w);
            }
        }
        __syncthreads();
    }
}

// ---------------------------------------------------------------------------
// GEMM1: g_h = relu(g_glimpse @ W1^T + b1)   M=512 N=1024 K=9216
// ---------------------------------------------------------------------------
__global__ __launch_bounds__(128)
void gemm1_tc_kernel(const float* __restrict__ W1, const float* __restrict__ b1)
{
    __shared__ uint32_t sA[2][BK * SMS];
    __shared__ uint32_t sB[2][BK * SMS];

    const int m0 = blockIdx.y * BM;
    const int n0 = blockIdx.x * BN;

    float acc[2][4][4] = {};
    gemm_phase(g_glimpse, DIN, W1, DIN, DIN, m0, n0, sA, sB, acc);

    const int lane = threadIdx.x & 31;
    const int warp = threadIdx.x >> 5;
    const int wm = (warp >> 1) * 32;
    const int wn = (warp & 1) * 32;
    const int g = lane >> 2;
    const int t = lane & 3;

    #pragma unroll
    for (int sm = 0; sm < 2; ++sm) {
        int mRow = m0 + wm + sm * 16 + g;
        #pragma unroll
        for (int n8 = 0; n8 < 4; ++n8) {
            int nCol = n0 + wn + n8 * 8 + 2 * t;
            float bb0 = b1[nCol], bb1 = b1[nCol + 1];
            float2 v0 = make_float2(fmaxf(acc[sm][n8][0] + bb0, 0.0f),
                                    fmaxf(acc[sm][n8][1] + bb1, 0.0f));
            float2 v1 = make_float2(fmaxf(acc[sm][n8][2] + bb0, 0.0f),
                                    fmaxf(acc[sm][n8][3] + bb1, 0.0f));
            *(float2*)&g_h[(long long)mRow * HG + nCol]       = v0;
            *(float2*)&g_h[(long long)(mRow + 8) * HG + nCol] = v1;
        }
    }
}

// ---------------------------------------------------------------------------
// GEMM2: out = relu(g_h @ W3^T + b3 + g_hw @ W4^T + b4)  M=512 N=1152
// ---------------------------------------------------------------------------
__global__ __launch_bounds__(128)
void gemm2_tc_kernel(const float* __restrict__ W3, const float* __restrict__ b3,
                     const float* __restrict__ W4, const float* __restrict__ b4,
                     float* __restrict__ out)
{
    __shared__ uint32_t sA[2][BK * SMS];
    __shared__ uint32_t sB[2][BK * SMS];

    const int m0 = blockIdx.y * BM;
    const int n0 = blockIdx.x * BN;

    float acc[2][4][4] = {};
    gemm_phase(g_h,  HG, W3, HG, HG, m0, n0, sA, sB, acc);   // K = 1024
    __syncthreads();
    gemm_phase(g_hw, HL, W4, HL, HL, m0, n0, sA, sB, acc);   // K = 128

    const int lane = threadIdx.x & 31;
    const int warp = threadIdx.x >> 5;
    const int wm = (warp >> 1) * 32;
    const int wn = (warp & 1) * 32;
    const int g = lane >> 2;
    const int t = lane & 3;

    #pragma unroll
    for (int sm = 0; sm < 2; ++sm) {
        int mRow = m0 + wm + sm * 16 + g;
        #pragma unroll
        for (int n8 = 0; n8 < 4; ++n8) {
            int nCol = n0 + wn + n8 * 8 + 2 * t;
            float bb0 = b3[nCol]     + b4[nCol];
            float bb1 = b3[nCol + 1] + b4[nCol + 1];
            float2 v0 = make_float2(fmaxf(acc[sm][n8][0] + bb0, 0.0f),
                                    fmaxf(acc[sm][n8][1] + bb1, 0.0f));
            float2 v1 = make_float2(fmaxf(acc[sm][n8][2] + bb0, 0.0f),
                                    fmaxf(acc[sm][n8][3] + bb1, 0.0f));
            *(float2*)&out[(long long)mRow * NOUT + nCol]       = v0;
            *(float2*)&out[(long long)(mRow + 8) * NOUT + nCol] = v1;
        }
    }
}

// ---------------------------------------------------------------------------
extern "C" void kernel_launch(void* const* d_in, const int* in_sizes, int n_in,
                              void* d_out, int out_size)
{
    const float* x  = (const float*)d_in[0];   // (512, 3, 256, 256)
    const float* l  = (const float*)d_in[1];   // (512, 2)
    const float* W1 = (const float*)d_in[2];   // (1024, 9216)
    const float* b1 = (const float*)d_in[3];   // (1024,)
    const float* W2 = (const float*)d_in[4];   // (128, 2)
    const float* b2 = (const float*)d_in[5];   // (128,)
    const float* W3 = (const float*)d_in[6];   // (1152, 1024)
    const float* b3 = (const float*)d_in[7];   // (1152,)
    const float* W4 = (const float*)d_in[8];   // (1152, 128)
    const float* b4 = (const float*)d_in[9];   // (1152,)
    float* out = (float*)d_out;                // (512, 1152)

    (void)in_sizes; (void)n_in; (void)out_size;

    // 1) foveation -> g_glimpse
    {
        int total = BATCH * DIN;
        foveate_kernel<<<(total + 255) / 256, 256>>>(x, l);
    }
    // 2) where path -> g_hw
    {
        int total = BATCH * HL;
        where_kernel<<<(total + 255) / 256, 256>>>(l, W2, b2);
    }
    // 3) h = relu(glimpse @ W1^T + b1)
    {
        dim3 grid(HG / BN, BATCH / BM);    // (16, 8) = 128 blocks
        gemm1_tc_kernel<<<grid, 128>>>(W1, b1);
    }
    // 4) out = relu(h @ W3^T + b3 + hw @ W4^T + b4)
    {
        dim3 grid(NOUT / BN, BATCH / BM);  // (18, 8) = 144 blocks
        gemm2_tc_kernel<<<grid, 128>>>(W3, b3, W4, b4, out);
    }
}

// round 10
// speedup vs baseline: 3.3435x; 1.6656x over previous
#include <cuda_runtime.h>
#include <cuda_bf16.h>
#include <cstdint>

// Problem constants
#define BATCH 512
#define CIN   3
#define HIMG  256
#define DIN   9216     // 3 scales * 3 ch * 32*32
#define HG    1024
#define HL    128
#define NOUT  1152     // HG + HL

#define BM 64
#define BN 64
#define BK 32
#define SMS 73         // smem row stride (conflict-free for transposed STS)

#define SPLIT1 4       // K-splits for GEMM1 (9216/4 = 2304)
#define SPLIT2 2       // K-splits for GEMM2 W3 phase (1024/2 = 512)

// Scratch (no allocations allowed -> device globals)
__device__ float g_glimpse[BATCH * DIN];            // 18.9 MB
__device__ float g_h[BATCH * HG];                   // 2 MB
__device__ float g_hw[BATCH * HL];                  // 256 KB
__device__ float g_part1[SPLIT1][BATCH * HG];       // 8 MB
__device__ float g_part2[SPLIT2][BATCH * NOUT];     // 4.7 MB

// ---------------------------------------------------------------------------
// Foveation (unchanged; passing since R2)
// ---------------------------------------------------------------------------
__global__ void foveate_kernel(const float* __restrict__ x,
                               const float* __restrict__ l)
{
    int idx = blockIdx.x * blockDim.x + threadIdx.x;
    if (idx >= BATCH * DIN) return;

    int b  = idx / DIN;
    int r  = idx % DIN;
    int pc = r >> 10;
    int i  = (r >> 5) & 31;
    int j  = r & 31;
    int p  = pc / 3;
    int c  = pc - 3 * p;
    int k  = 1 << p;
    int pad = 16 * k;

    float l0 = l[2 * b + 0];
    float l1 = l[2 * b + 1];
    int fx = (int)floorf(0.5f * ((l0 + 1.0f) * 256.0f));
    int fy = (int)floorf(0.5f * ((l1 + 1.0f) * 256.0f));
    fx = min(max(fx, 0), 256);
    fy = min(max(fy, 0), 256);

    int y0 = fy + i * k - pad;
    int x0 = fx + j * k - pad;

    const float* src = x + ((long long)b * CIN + c) * (HIMG * HIMG);
    float s = 0.0f;
    #pragma unroll 4
    for (int di = 0; di < k; ++di) {
        int y = y0 + di;
        if ((unsigned)y < 256u) {
            const float* row = src + y * HIMG;
            #pragma unroll 4
            for (int dj = 0; dj < k; ++dj) {
                int xx = x0 + dj;
                if ((unsigned)xx < 256u) s += row[xx];
            }
        }
    }
    g_glimpse[idx] = s / (float)(k * k);
}

// ---------------------------------------------------------------------------
// hw = relu(l @ W2^T + b2)
// ---------------------------------------------------------------------------
__global__ void where_kernel(const float* __restrict__ l,
                             const float* __restrict__ W2,
                             const float* __restrict__ b2)
{
    int idx = blockIdx.x * blockDim.x + threadIdx.x;
    if (idx >= BATCH * HL) return;
    int b = idx / HL;
    int n = idx % HL;
    float v = b2[n] + l[2 * b + 0] * W2[2 * n + 0] + l[2 * b + 1] * W2[2 * n + 1];
    g_hw[idx] = fmaxf(v, 0.0f);
}

// ---------------------------------------------------------------------------
// TF32 tensor-core GEMM machinery (m16n8k8 warp mma)
// ---------------------------------------------------------------------------
__device__ __forceinline__ uint32_t f2tf32(float f) {
    uint32_t u;
    asm("cvt.rna.tf32.f32 %0, %1;" : "=r"(u) : "f"(f));
    return u;
}

__device__ __forceinline__ void mma_tf32(float c[4],
                                         const uint32_t a[4],
                                         const uint32_t b[2]) {
    asm volatile(
        "mma.sync.aligned.m16n8k8.row.col.f32.tf32.tf32.f32 "
        "{%0,%1,%2,%3}, {%4,%5,%6,%7}, {%8,%9}, {%0,%1,%2,%3};"
        : "+f"(c[0]), "+f"(c[1]), "+f"(c[2]), "+f"(c[3])
        : "r"(a[0]), "r"(a[1]), "r"(a[2]), "r"(a[3]),
          "r"(b[0]), "r"(b[1]));
}

__device__ __forceinline__ void mma_compute(const uint32_t* __restrict__ sa,
                                            const uint32_t* __restrict__ sb,
                                            int wm, int wn, int g, int t,
                                            float acc[2][4][4])
{
    #pragma unroll
    for (int ks = 0; ks < BK; ks += 8) {
        const uint32_t* pa0 = sa + (ks + t) * SMS;
        const uint32_t* pa4 = sa + (ks + t + 4) * SMS;
        const uint32_t* pb0 = sb + (ks + t) * SMS;
        const uint32_t* pb4 = sb + (ks + t + 4) * SMS;

        uint32_t af[2][4];
        #pragma unroll
        for (int sm = 0; sm < 2; ++sm) {
            int mm = wm + sm * 16 + g;
            af[sm][0] = pa0[mm];
            af[sm][1] = pa0[mm + 8];
            af[sm][2] = pa4[mm];
            af[sm][3] = pa4[mm + 8];
        }
        uint32_t bf[4][2];
        #pragma unroll
        for (int n8 = 0; n8 < 4; ++n8) {
            int nn = wn + n8 * 8 + g;
            bf[n8][0] = pb0[nn];
            bf[n8][1] = pb4[nn];
        }
        #pragma unroll
        for (int sm = 0; sm < 2; ++sm)
            #pragma unroll
            for (int n8 = 0; n8 < 4; ++n8)
                mma_tf32(acc[sm][n8], af[sm], bf[n8]);
    }
}

// One pipelined GEMM phase: acc += A[m0.., k0:k0+K] @ W[n0.., k0:k0+K]^T
// A/W row-major. K % 32 == 0.
__device__ __forceinline__ void gemm_phase(const float* __restrict__ A, int lda,
                                           const float* __restrict__ W, int ldw,
                                           int K, int m0, int n0,
                                           uint32_t (*sA)[BK * SMS],
                                           uint32_t (*sB)[BK * SMS],
                                           float acc[2][4][4])
{
    const int tid  = threadIdx.x;
    const int lane = tid & 31;
    const int warp = tid >> 5;
    const int wm = (warp >> 1) * 32;
    const int wn = (warp & 1) * 32;
    const int g = lane >> 2;
    const int t = lane & 3;

    const int nIter = K / BK;
    float4 ra[4], rb[4];

    int rowi[4], ki[4];
    #pragma unroll
    for (int i = 0; i < 4; ++i) {
        int idx = tid + 128 * i;
        rowi[i] = idx >> 3;
        ki[i]   = (idx & 7) * 4;
    }

    #pragma unroll
    for (int i = 0; i < 4; ++i) {
        ra[i] = *(const float4*)(A + (long long)(m0 + rowi[i]) * lda + ki[i]);
        rb[i] = *(const float4*)(W + (long long)(n0 + rowi[i]) * ldw + ki[i]);
    }
    #pragma unroll
    for (int i = 0; i < 4; ++i) {
        int base = ki[i] * SMS + rowi[i];
        sA[0][base + 0 * SMS] = f2tf32(ra[i].x);
        sA[0][base + 1 * SMS] = f2tf32(ra[i].y);
        sA[0][base + 2 * SMS] = f2tf32(ra[i].z);
        sA[0][base + 3 * SMS] = f2tf32(ra[i].w);
        sB[0][base + 0 * SMS] = f2tf32(rb[i].x);
        sB[0][base + 1 * SMS] = f2tf32(rb[i].y);
        sB[0][base + 2 * SMS] = f2tf32(rb[i].z);
        sB[0][base + 3 * SMS] = f2tf32(rb[i].w);
    }
    __syncthreads();

    for (int it = 0; it < nIter; ++it) {
        int nxt = it + 1;
        if (nxt < nIter) {
            int k0 = nxt * BK;
            #pragma unroll
            for (int i = 0; i < 4; ++i) {
                ra[i] = *(const float4*)(A + (long long)(m0 + rowi[i]) * lda + k0 + ki[i]);
                rb[i] = *(const float4*)(W + (long long)(n0 + rowi[i]) * ldw + k0 + ki[i]);
            }
        }

        mma_compute(sA[it & 1], sB[it & 1], wm, wn, g, t, acc);

        if (nxt < nIter) {
            int buf = nxt & 1;
            #pragma unroll
            for (int i = 0; i < 4; ++i) {
                int base = ki[i] * SMS + rowi[i];
                sA[buf][base + 0 * SMS] = f2tf32(ra[i].x);
                sA[buf][base + 1 * SMS] = f2tf32(ra[i].y);
                sA[buf][base + 2 * SMS] = f2tf32(ra[i].z);
                sA[buf][base + 3 * SMS] = f2tf32(ra[i].w);
                sB[buf][base + 0 * SMS] = f2tf32(rb[i].x);
                sB[buf][base + 1 * SMS] = f2tf32(rb[i].y);
                sB[buf][base + 2 * SMS] = f2tf32(rb[i].z);
                sB[buf][base + 3 * SMS] = f2tf32(rb[i].w);
            }
        }
        __syncthreads();
    }
}

// Store raw accumulators to a partial buffer (row stride N).
__device__ __forceinline__ void store_partial(float* __restrict__ P, int N,
                                              int m0, int n0,
                                              const float acc[2][4][4])
{
    const int lane = threadIdx.x & 31;
    const int warp = threadIdx.x >> 5;
    const int wm = (warp >> 1) * 32;
    const int wn = (warp & 1) * 32;
    const int g = lane >> 2;
    const int t = lane & 3;

    #pragma unroll
    for (int sm = 0; sm < 2; ++sm) {
        int mRow = m0 + wm + sm * 16 + g;
        #pragma unroll
        for (int n8 = 0; n8 < 4; ++n8) {
            int nCol = n0 + wn + n8 * 8 + 2 * t;
            *(float2*)&P[(long long)mRow * N + nCol] =
                make_float2(acc[sm][n8][0], acc[sm][n8][1]);
            *(float2*)&P[(long long)(mRow + 8) * N + nCol] =
                make_float2(acc[sm][n8][2], acc[sm][n8][3]);
        }
    }
}

// ---------------------------------------------------------------------------
// GEMM1 split-K: g_part1[s] = glimpse[:, sK:(s+1)K] @ W1[:, sK:(s+1)K]^T
// ---------------------------------------------------------------------------
__global__ __launch_bounds__(128)
void gemm1_tc_kernel(const float* __restrict__ W1)
{
    __shared__ uint32_t sA[2][BK * SMS];
    __shared__ uint32_t sB[2][BK * SMS];

    const int m0 = blockIdx.y * BM;
    const int n0 = blockIdx.x * BN;
    const int s  = blockIdx.z;
    const int Ks = DIN / SPLIT1;              // 2304
    const int k0 = s * Ks;

    float acc[2][4][4] = {};
    gemm_phase(g_glimpse + k0, DIN, W1 + k0, DIN, Ks, m0, n0, sA, sB, acc);
    store_partial(g_part1[s], HG, m0, n0, acc);
}

// reduce: g_h = relu(sum_s part1[s] + b1)
__global__ void reduce1_kernel(const float* __restrict__ b1)
{
    int idx = (blockIdx.x * blockDim.x + threadIdx.x) * 4;
    if (idx >= BATCH * HG) return;
    float4 v = *(const float4*)&g_part1[0][idx];
    #pragma unroll
    for (int s = 1; s < SPLIT1; ++s) {
        float4 p = *(const float4*)&g_part1[s][idx];
        v.x += p.x; v.y += p.y; v.z += p.z; v.w += p.w;
    }
    int n = idx & (HG - 1);
    float4 bb = *(const float4*)&b1[n];
    v.x = fmaxf(v.x + bb.x, 0.0f);
    v.y = fmaxf(v.y + bb.y, 0.0f);
    v.z = fmaxf(v.z + bb.z, 0.0f);
    v.w = fmaxf(v.w + bb.w, 0.0f);
    *(float4*)&g_h[idx] = v;
}

// ---------------------------------------------------------------------------
// GEMM2 split-K: s=0 -> h[:, 0:512] @ W3^T slice  +  hw @ W4^T (K=128)
//                s=1 -> h[:, 512:1024] @ W3^T slice
// ---------------------------------------------------------------------------
__global__ __launch_bounds__(128)
void gemm2_tc_kernel(const float* __restrict__ W3,
                     const float* __restrict__ W4)
{
    __shared__ uint32_t sA[2][BK * SMS];
    __shared__ uint32_t sB[2][BK * SMS];

    const int m0 = blockIdx.y * BM;
    const int n0 = blockIdx.x * BN;
    const int s  = blockIdx.z;
    const int Ks = HG / SPLIT2;               // 512
    const int k0 = s * Ks;

    float acc[2][4][4] = {};
    gemm_phase(g_h + k0, HG, W3 + k0, HG, Ks, m0, n0, sA, sB, acc);
    if (s == 0) {
        __syncthreads();
        gemm_phase(g_hw, HL, W4, HL, HL, m0, n0, sA, sB, acc);
    }
    store_partial(g_part2[s], NOUT, m0, n0, acc);
}

// reduce: out = relu(sum_s part2[s] + b3 + b4)
__global__ void reduce2_kernel(const float* __restrict__ b3,
                               const float* __restrict__ b4,
                               float* __restrict__ out)
{
    int idx = (blockIdx.x * blockDim.x + threadIdx.x) * 4;
    if (idx >= BATCH * NOUT) return;
    float4 v = *(const float4*)&g_part2[0][idx];
    #pragma unroll
    for (int s = 1; s < SPLIT2; ++s) {
        float4 p = *(const float4*)&g_part2[s][idx];
        v.x += p.x; v.y += p.y; v.z += p.z; v.w += p.w;
    }
    int n = idx % NOUT;
    float4 b3v = *(const float4*)&b3[n];
    float4 b4v = *(const float4*)&b4[n];
    v.x = fmaxf(v.x + b3v.x + b4v.x, 0.0f);
    v.y = fmaxf(v.y + b3v.y + b4v.y, 0.0f);
    v.z = fmaxf(v.z + b3v.z + b4v.z, 0.0f);
    v.w = fmaxf(v.w + b3v.w + b4v.w, 0.0f);
    *(float4*)&out[idx] = v;
}

// ---------------------------------------------------------------------------
extern "C" void kernel_launch(void* const* d_in, const int* in_sizes, int n_in,
                              void* d_out, int out_size)
{
    const float* x  = (const float*)d_in[0];   // (512, 3, 256, 256)
    const float* l  = (const float*)d_in[1];   // (512, 2)
    const float* W1 = (const float*)d_in[2];   // (1024, 9216)
    const float* b1 = (const float*)d_in[3];   // (1024,)
    const float* W2 = (const float*)d_in[4];   // (128, 2)
    const float* b2 = (const float*)d_in[5];   // (128,)
    const float* W3 = (const float*)d_in[6];   // (1152, 1024)
    const float* b3 = (const float*)d_in[7];   // (1152,)
    const float* W4 = (const float*)d_in[8];   // (1152, 128)
    const float* b4 = (const float*)d_in[9];   // (1152,)
    float* out = (float*)d_out;                // (512, 1152)

    (void)in_sizes; (void)n_in; (void)out_size;

    // 1) foveation -> g_glimpse
    {
        int total = BATCH * DIN;
        foveate_kernel<<<(total + 255) / 256, 256>>>(x, l);
    }
    // 2) where path -> g_hw
    {
        int total = BATCH * HL;
        where_kernel<<<(total + 255) / 256, 256>>>(l, W2, b2);
    }
    // 3) h = relu(glimpse @ W1^T + b1) via split-K partials + reduce
    {
        dim3 grid(HG / BN, BATCH / BM, SPLIT1);   // (16, 8, 4) = 512 blocks
        gemm1_tc_kernel<<<grid, 128>>>(W1);
        int total = BATCH * HG / 4;
        reduce1_kernel<<<(total + 255) / 256, 256>>>(b1);
    }
    // 4) out = relu(h @ W3^T + b3 + hw @ W4^T + b4) via split-K + reduce
    {
        dim3 grid(NOUT / BN, BATCH / BM, SPLIT2); // (18, 8, 2) = 288 blocks
        gemm2_tc_kernel<<<grid, 128>>>(W3, W4);
        int total = BATCH * NOUT / 4;
        reduce2_kernel<<<(total + 255) / 256, 256>>>(b3, b4, out);
    }
}

// round 13
// speedup vs baseline: 3.9303x; 1.1755x over previous
#include <cuda_runtime.h>
#include <cuda_bf16.h>
#include <cstdint>

// Problem constants
#define BATCH 512
#define CIN   3
#define HIMG  256
#define DIN   9216     // 3 scales * 3 ch * 32*32
#define HG    1024
#define HL    128
#define NOUT  1152     // HG + HL

// GEMM2 (64x64) params
#define BM 64
#define BN 64
#define BK 32
#define SMS 73

// GEMM1 (128x128) params
#define BM1 128
#define BN1 128
#define BK1 16
#define SMS1 134       // 134 mod 32 = 6 -> STS banks 6k+row cover all 32

#define SPLIT1 8       // K-splits for GEMM1 (9216/8 = 1152)
#define SPLIT2 2       // K-splits for GEMM2 W3 phase (1024/2 = 512)

// Scratch (no allocations allowed -> device globals)
__device__ float g_glimpse[BATCH * DIN];            // 18.9 MB
__device__ float g_h[BATCH * HG];                   // 2 MB
__device__ float g_hw[BATCH * HL];                  // 256 KB
__device__ float g_part1[SPLIT1][BATCH * HG];       // 16 MB
__device__ float g_part2[SPLIT2][BATCH * NOUT];     // 4.7 MB

// ---------------------------------------------------------------------------
// Foveation v2: hierarchical pooling. One block per (b, c).
// Loads the 128x128 window once (as 2x2 quads), emits:
//   scale0 = raw central 32x32
//   scale1 = central 32x32 of quad-sums / 4
//   scale2 = 2x2 of quad-sums / 16
// ---------------------------------------------------------------------------
__global__ __launch_bounds__(256)
void foveate2_kernel(const float* __restrict__ x,
                     const float* __restrict__ l)
{
    __shared__ float p1[64 * 64];   // quad sums (16 KB)

    const int bid = blockIdx.x;
    const int b = bid / 3;
    const int c = bid - 3 * b;
    const int tid = threadIdx.x;

    float l0 = l[2 * b + 0];
    float l1 = l[2 * b + 1];
    int fx = (int)floorf(0.5f * ((l0 + 1.0f) * 256.0f));
    int fy = (int)floorf(0.5f * ((l1 + 1.0f) * 256.0f));
    fx = min(max(fx, 0), 256);
    fy = min(max(fy, 0), 256);

    const int y0 = fy - 64;
    const int x0 = fx - 64;

    const float* __restrict__ src = x + ((long long)b * CIN + c) * (HIMG * HIMG);
    float* __restrict__ gout = g_glimpse + (long long)b * DIN + c * 1024;

    #pragma unroll
    for (int i = 0; i < 16; ++i) {
        int q  = tid + 256 * i;          // 0..4095
        int qy = q >> 6;
        int qx = q & 63;
        int yb = y0 + 2 * qy;
        int xb = x0 + 2 * qx;

        float v00 = 0.0f, v01 = 0.0f, v10 = 0.0f, v11 = 0.0f;
        bool xi0 = (unsigned)xb < 256u;
        bool xi1 = (unsigned)(xb + 1) < 256u;
        if ((unsigned)yb < 256u) {
            const float* r = src + yb * HIMG;
            if (xi0) v00 = r[xb];
            if (xi1) v01 = r[xb + 1];
        }
        if ((unsigned)(yb + 1) < 256u) {
            const float* r = src + (yb + 1) * HIMG;
            if (xi0) v10 = r[xb];
            if (xi1) v11 = r[xb + 1];
        }
        p1[q] = v00 + v01 + v10 + v11;

        // scale0: raw pixels of central 32x32 window (rows 48..79 of tile)
        if (qy >= 24 && qy < 40 && qx >= 24 && qx < 40) {
            int i0 = 2 * qy - 48;
            int j0 = 2 * qx - 48;
            gout[i0 * 32 + j0]           = v00;
            gout[i0 * 32 + j0 + 1]       = v01;
            gout[(i0 + 1) * 32 + j0]     = v10;
            gout[(i0 + 1) * 32 + j0 + 1] = v11;
        }
    }
    __syncthreads();

    #pragma unroll
    for (int i = 0; i < 4; ++i) {
        int o  = tid + 256 * i;          // 0..1023
        int oi = o >> 5;
        int oj = o & 31;
        // scale1: central 32x32 of p1, /4
        gout[3072 + o] = p1[(16 + oi) * 64 + (16 + oj)] * 0.25f;
        // scale2: 2x2 of p1, /16
        float s = p1[(2 * oi) * 64 + 2 * oj]
                + p1[(2 * oi) * 64 + 2 * oj + 1]
                + p1[(2 * oi + 1) * 64 + 2 * oj]
                + p1[(2 * oi + 1) * 64 + 2 * oj + 1];
        gout[6144 + o] = s * 0.0625f;
    }
}

// ---------------------------------------------------------------------------
// hw = relu(l @ W2^T + b2)
// ---------------------------------------------------------------------------
__global__ void where_kernel(const float* __restrict__ l,
                             const float* __restrict__ W2,
                             const float* __restrict__ b2)
{
    int idx = blockIdx.x * blockDim.x + threadIdx.x;
    if (idx >= BATCH * HL) return;
    int b = idx / HL;
    int n = idx % HL;
    float v = b2[n] + l[2 * b + 0] * W2[2 * n + 0] + l[2 * b + 1] * W2[2 * n + 1];
    g_hw[idx] = fmaxf(v, 0.0f);
}

// ---------------------------------------------------------------------------
// TF32 tensor-core machinery
// ---------------------------------------------------------------------------
__device__ __forceinline__ uint32_t f2tf32(float f) {
    uint32_t u;
    asm("cvt.rna.tf32.f32 %0, %1;" : "=r"(u) : "f"(f));
    return u;
}

__device__ __forceinline__ void mma_tf32(float c[4],
                                         const uint32_t a[4],
                                         const uint32_t b[2]) {
    asm volatile(
        "mma.sync.aligned.m16n8k8.row.col.f32.tf32.tf32.f32 "
        "{%0,%1,%2,%3}, {%4,%5,%6,%7}, {%8,%9}, {%0,%1,%2,%3};"
        : "+f"(c[0]), "+f"(c[1]), "+f"(c[2]), "+f"(c[3])
        : "r"(a[0]), "r"(a[1]), "r"(a[2]), "r"(a[3]),
          "r"(b[0]), "r"(b[1]));
}

// ===========================================================================
// GEMM1: 128x128 tiles, BK=16, 256 threads (8 warps of 64x32)
// ===========================================================================
__device__ __forceinline__ void mma_compute1(const uint32_t* __restrict__ sa,
                                             const uint32_t* __restrict__ sb,
                                             int wm, int wn, int g, int t,
                                             float acc[4][4][4])
{
    #pragma unroll
    for (int ks = 0; ks < BK1; ks += 8) {
        const uint32_t* pa0 = sa + (ks + t) * SMS1;
        const uint32_t* pa4 = sa + (ks + t + 4) * SMS1;
        const uint32_t* pb0 = sb + (ks + t) * SMS1;
        const uint32_t* pb4 = sb + (ks + t + 4) * SMS1;

        uint32_t af[4][4];
        #pragma unroll
        for (int mf = 0; mf < 4; ++mf) {
            int mm = wm + mf * 16 + g;
            af[mf][0] = pa0[mm];
            af[mf][1] = pa0[mm + 8];
            af[mf][2] = pa4[mm];
            af[mf][3] = pa4[mm + 8];
        }
        uint32_t bf[4][2];
        #pragma unroll
        for (int nf = 0; nf < 4; ++nf) {
            int nn = wn + nf * 8 + g;
            bf[nf][0] = pb0[nn];
            bf[nf][1] = pb4[nn];
        }
        #pragma unroll
        for (int mf = 0; mf < 4; ++mf)
            #pragma unroll
            for (int nf = 0; nf < 4; ++nf)
                mma_tf32(acc[mf][nf], af[mf], bf[nf]);
    }
}

__global__ __launch_bounds__(256)
void gemm1_tc_kernel(const float* __restrict__ W1)
{
    __shared__ uint32_t sA[2][BK1 * SMS1];
    __shared__ uint32_t sB[2][BK1 * SMS1];

    const int m0 = blockIdx.y * BM1;
    const int n0 = blockIdx.x * BN1;
    const int s  = blockIdx.z;
    const int Ks = DIN / SPLIT1;            // 1152
    const float* __restrict__ A = g_glimpse + s * Ks;
    const float* __restrict__ W = W1 + s * Ks;

    const int tid  = threadIdx.x;
    const int lane = tid & 31;
    const int warp = tid >> 5;
    const int wm = (warp >> 2) * 64;        // 0 or 64
    const int wn = (warp & 3) * 32;         // 0,32,64,96
    const int g = lane >> 2;
    const int t = lane & 3;

    float acc[4][4][4] = {};

    // load coords: 128 rows x 16 k = 512 float4 / 256 thr = 2 each
    int rowi[2], ki[2];
    #pragma unroll
    for (int i = 0; i < 2; ++i) {
        int idx = tid + 256 * i;
        rowi[i] = idx >> 2;
        ki[i]   = (idx & 3) * 4;
    }

    float4 ra[2], rb[2];
    #pragma unroll
    for (int i = 0; i < 2; ++i) {
        ra[i] = *(const float4*)(A + (long long)(m0 + rowi[i]) * DIN + ki[i]);
        rb[i] = *(const float4*)(W + (long long)(n0 + rowi[i]) * DIN + ki[i]);
    }
    #pragma unroll
    for (int i = 0; i < 2; ++i) {
        int base = ki[i] * SMS1 + rowi[i];
        sA[0][base + 0 * SMS1] = f2tf32(ra[i].x);
        sA[0][base + 1 * SMS1] = f2tf32(ra[i].y);
        sA[0][base + 2 * SMS1] = f2tf32(ra[i].z);
        sA[0][base + 3 * SMS1] = f2tf32(ra[i].w);
        sB[0][base + 0 * SMS1] = f2tf32(rb[i].x);
        sB[0][base + 1 * SMS1] = f2tf32(rb[i].y);
        sB[0][base + 2 * SMS1] = f2tf32(rb[i].z);
        sB[0][base + 3 * SMS1] = f2tf32(rb[i].w);
    }
    __syncthreads();

    const int nIter = Ks / BK1;             // 72
    for (int it = 0; it < nIter; ++it) {
        int nxt = it + 1;
        if (nxt < nIter) {
            int k0 = nxt * BK1;
            #pragma unroll
            for (int i = 0; i < 2; ++i) {
                ra[i] = *(const float4*)(A + (long long)(m0 + rowi[i]) * DIN + k0 + ki[i]);
                rb[i] = *(const float4*)(W + (long long)(n0 + rowi[i]) * DIN + k0 + ki[i]);
            }
        }

        mma_compute1(sA[it & 1], sB[it & 1], wm, wn, g, t, acc);

        if (nxt < nIter) {
            int buf = nxt & 1;
            #pragma unroll
            for (int i = 0; i < 2; ++i) {
                int base = ki[i] * SMS1 + rowi[i];
                sA[buf][base + 0 * SMS1] = f2tf32(ra[i].x);
                sA[buf][base + 1 * SMS1] = f2tf32(ra[i].y);
                sA[buf][base + 2 * SMS1] = f2tf32(ra[i].z);
                sA[buf][base + 3 * SMS1] = f2tf32(ra[i].w);
                sB[buf][base + 0 * SMS1] = f2tf32(rb[i].x);
                sB[buf][base + 1 * SMS1] = f2tf32(rb[i].y);
                sB[buf][base + 2 * SMS1] = f2tf32(rb[i].z);
                sB[buf][base + 3 * SMS1] = f2tf32(rb[i].w);
            }
        }
        __syncthreads();
    }

    // store raw partials
    float* __restrict__ P = g_part1[s];
    #pragma unroll
    for (int mf = 0; mf < 4; ++mf) {
        int mRow = m0 + wm + mf * 16 + g;
        #pragma unroll
        for (int nf = 0; nf < 4; ++nf) {
            int nCol = n0 + wn + nf * 8 + 2 * t;
            *(float2*)&P[(long long)mRow * HG + nCol] =
                make_float2(acc[mf][nf][0], acc[mf][nf][1]);
            *(float2*)&P[(long long)(mRow + 8) * HG + nCol] =
                make_float2(acc[mf][nf][2], acc[mf][nf][3]);
        }
    }
}

// reduce: g_h = relu(sum_s part1[s] + b1)
__global__ void reduce1_kernel(const float* __restrict__ b1)
{
    int idx = (blockIdx.x * blockDim.x + threadIdx.x) * 4;
    if (idx >= BATCH * HG) return;
    float4 v = *(const float4*)&g_part1[0][idx];
    #pragma unroll
    for (int s = 1; s < SPLIT1; ++s) {
        float4 p = *(const float4*)&g_part1[s][idx];
        v.x += p.x; v.y += p.y; v.z += p.z; v.w += p.w;
    }
    int n = idx & (HG - 1);
    float4 bb = *(const float4*)&b1[n];
    v.x = fmaxf(v.x + bb.x, 0.0f);
    v.y = fmaxf(v.y + bb.y, 0.0f);
    v.z = fmaxf(v.z + bb.z, 0.0f);
    v.w = fmaxf(v.w + bb.w, 0.0f);
    *(float4*)&g_h[idx] = v;
}

// ===========================================================================
// GEMM2: 64x64 tiles (unchanged machinery)
// ===========================================================================
__device__ __forceinline__ void mma_compute(const uint32_t* __restrict__ sa,
                                            const uint32_t* __restrict__ sb,
                                            int wm, int wn, int g, int t,
                                            float acc[2][4][4])
{
    #pragma unroll
    for (int ks = 0; ks < BK; ks += 8) {
        const uint32_t* pa0 = sa + (ks + t) * SMS;
        const uint32_t* pa4 = sa + (ks + t + 4) * SMS;
        const uint32_t* pb0 = sb + (ks + t) * SMS;
        const uint32_t* pb4 = sb + (ks + t + 4) * SMS;

        uint32_t af[2][4];
        #pragma unroll
        for (int sm = 0; sm < 2; ++sm) {
            int mm = wm + sm * 16 + g;
            af[sm][0] = pa0[mm];
            af[sm][1] = pa0[mm + 8];
            af[sm][2] = pa4[mm];
            af[sm][3] = pa4[mm + 8];
        }
        uint32_t bf[4][2];
        #pragma unroll
        for (int n8 = 0; n8 < 4; ++n8) {
            int nn = wn + n8 * 8 + g;
            bf[n8][0] = pb0[nn];
            bf[n8][1] = pb4[nn];
        }
        #pragma unroll
        for (int sm = 0; sm < 2; ++sm)
            #pragma unroll
            for (int n8 = 0; n8 < 4; ++n8)
                mma_tf32(acc[sm][n8], af[sm], bf[n8]);
    }
}

__device__ __forceinline__ void gemm_phase(const float* __restrict__ A, int lda,
                                           const float* __restrict__ W, int ldw,
                                           int K, int m0, int n0,
                                           uint32_t (*sA)[BK * SMS],
                                           uint32_t (*sB)[BK * SMS],
                                           float acc[2][4][4])
{
    const int tid  = threadIdx.x;
    const int lane = tid & 31;
    const int warp = tid >> 5;
    const int wm = (warp >> 1) * 32;
    const int wn = (warp & 1) * 32;
    const int g = lane >> 2;
    const int t = lane & 3;

    const int nIter = K / BK;
    float4 ra[4], rb[4];

    int rowi[4], ki[4];
    #pragma unroll
    for (int i = 0; i < 4; ++i) {
        int idx = tid + 128 * i;
        rowi[i] = idx >> 3;
        ki[i]   = (idx & 7) * 4;
    }

    #pragma unroll
    for (int i = 0; i < 4; ++i) {
        ra[i] = *(const float4*)(A + (long long)(m0 + rowi[i]) * lda + ki[i]);
        rb[i] = *(const float4*)(W + (long long)(n0 + rowi[i]) * ldw + ki[i]);
    }
    #pragma unroll
    for (int i = 0; i < 4; ++i) {
        int base = ki[i] * SMS + rowi[i];
        sA[0][base + 0 * SMS] = f2tf32(ra[i].x);
        sA[0][base + 1 * SMS] = f2tf32(ra[i].y);
        sA[0][base + 2 * SMS] = f2tf32(ra[i].z);
        sA[0][base + 3 * SMS] = f2tf32(ra[i].w);
        sB[0][base + 0 * SMS] = f2tf32(rb[i].x);
        sB[0][base + 1 * SMS] = f2tf32(rb[i].y);
        sB[0][base + 2 * SMS] = f2tf32(rb[i].z);
        sB[0][base + 3 * SMS] = f2tf32(rb[i].w);
    }
    __syncthreads();

    for (int it = 0; it < nIter; ++it) {
        int nxt = it + 1;
        if (nxt < nIter) {
            int k0 = nxt * BK;
            #pragma unroll
            for (int i = 0; i < 4; ++i) {
                ra[i] = *(const float4*)(A + (long long)(m0 + rowi[i]) * lda + k0 + ki[i]);
                rb[i] = *(const float4*)(W + (long long)(n0 + rowi[i]) * ldw + k0 + ki[i]);
            }
        }

        mma_compute(sA[it & 1], sB[it & 1], wm, wn, g, t, acc);

        if (nxt < nIter) {
            int buf = nxt & 1;
            #pragma unroll
            for (int i = 0; i < 4; ++i) {
                int base = ki[i] * SMS + rowi[i];
                sA[buf][base + 0 * SMS] = f2tf32(ra[i].x);
                sA[buf][base + 1 * SMS] = f2tf32(ra[i].y);
                sA[buf][base + 2 * SMS] = f2tf32(ra[i].z);
                sA[buf][base + 3 * SMS] = f2tf32(ra[i].w);
                sB[buf][base + 0 * SMS] = f2tf32(rb[i].x);
                sB[buf][base + 1 * SMS] = f2tf32(rb[i].y);
                sB[buf][base + 2 * SMS] = f2tf32(rb[i].z);
                sB[buf][base + 3 * SMS] = f2tf32(rb[i].w);
            }
        }
        __syncthreads();
    }
}

__device__ __forceinline__ void store_partial(float* __restrict__ P, int N,
                                              int m0, int n0,
                                              const float acc[2][4][4])
{
    const int lane = threadIdx.x & 31;
    const int warp = threadIdx.x >> 5;
    const int wm = (warp >> 1) * 32;
    const int wn = (warp & 1) * 32;
    const int g = lane >> 2;
    const int t = lane & 3;

    #pragma unroll
    for (int sm = 0; sm < 2; ++sm) {
        int mRow = m0 + wm + sm * 16 + g;
        #pragma unroll
        for (int n8 = 0; n8 < 4; ++n8) {
            int nCol = n0 + wn + n8 * 8 + 2 * t;
            *(float2*)&P[(long long)mRow * N + nCol] =
                make_float2(acc[sm][n8][0], acc[sm][n8][1]);
            *(float2*)&P[(long long)(mRow + 8) * N + nCol] =
                make_float2(acc[sm][n8][2], acc[sm][n8][3]);
        }
    }
}

__global__ __launch_bounds__(128)
void gemm2_tc_kernel(const float* __restrict__ W3,
                     const float* __restrict__ W4)
{
    __shared__ uint32_t sA[2][BK * SMS];
    __shared__ uint32_t sB[2][BK * SMS];

    const int m0 = blockIdx.y * BM;
    const int n0 = blockIdx.x * BN;
    const int s  = blockIdx.z;
    const int Ks = HG / SPLIT2;               // 512
    const int k0 = s * Ks;

    float acc[2][4][4] = {};
    gemm_phase(g_h + k0, HG, W3 + k0, HG, Ks, m0, n0, sA, sB, acc);
    if (s == 0) {
        __syncthreads();
        gemm_phase(g_hw, HL, W4, HL, HL, m0, n0, sA, sB, acc);
    }
    store_partial(g_part2[s], NOUT, m0, n0, acc);
}

__global__ void reduce2_kernel(const float* __restrict__ b3,
                               const float* __restrict__ b4,
                               float* __restrict__ out)
{
    int idx = (blockIdx.x * blockDim.x + threadIdx.x) * 4;
    if (idx >= BATCH * NOUT) return;
    float4 v = *(const float4*)&g_part2[0][idx];
    #pragma unroll
    for (int s = 1; s < SPLIT2; ++s) {
        float4 p = *(const float4*)&g_part2[s][idx];
        v.x += p.x; v.y += p.y; v.z += p.z; v.w += p.w;
    }
    int n = idx % NOUT;
    float4 b3v = *(const float4*)&b3[n];
    float4 b4v = *(const float4*)&b4[n];
    v.x = fmaxf(v.x + b3v.x + b4v.x, 0.0f);
    v.y = fmaxf(v.y + b3v.y + b4v.y, 0.0f);
    v.z = fmaxf(v.z + b3v.z + b4v.z, 0.0f);
    v.w = fmaxf(v.w + b3v.w + b4v.w, 0.0f);
    *(float4*)&out[idx] = v;
}

// ---------------------------------------------------------------------------
extern "C" void kernel_launch(void* const* d_in, const int* in_sizes, int n_in,
                              void* d_out, int out_size)
{
    const float* x  = (const float*)d_in[0];
    const float* l  = (const float*)d_in[1];
    const float* W1 = (const float*)d_in[2];
    const float* b1 = (const float*)d_in[3];
    const float* W2 = (const float*)d_in[4];
    const float* b2 = (const float*)d_in[5];
    const float* W3 = (const float*)d_in[6];
    const float* b3 = (const float*)d_in[7];
    const float* W4 = (const float*)d_in[8];
    const float* b4 = (const float*)d_in[9];
    float* out = (float*)d_out;

    (void)in_sizes; (void)n_in; (void)out_size;

    // 1) foveation (hierarchical) -> g_glimpse
    foveate2_kernel<<<BATCH * CIN, 256>>>(x, l);

    // 2) where path -> g_hw
    {
        int total = BATCH * HL;
        where_kernel<<<(total + 255) / 256, 256>>>(l, W2, b2);
    }
    // 3) h = relu(glimpse @ W1^T + b1) via 128x128 split-K + reduce
    {
        dim3 grid(HG / BN1, BATCH / BM1, SPLIT1);  // (8, 4, 8) = 256 blocks
        gemm1_tc_kernel<<<grid, 256>>>(W1);
        int total = BATCH * HG / 4;
        reduce1_kernel<<<(total + 255) / 256, 256>>>(b1);
    }
    // 4) out = relu(h @ W3^T + b3 + hw @ W4^T + b4) via split-K + reduce
    {
        dim3 grid(NOUT / BN, BATCH / BM, SPLIT2);  // (18, 8, 2) = 288 blocks
        gemm2_tc_kernel<<<grid, 128>>>(W3, W4);
        int total = BATCH * NOUT / 4;
        reduce2_kernel<<<(total + 255) / 256, 256>>>(b3, b4, out);
    }
}